// round 9
// baseline (speedup 1.0000x reference)
#include <cuda_runtime.h>

#define TPB  256
#define MAXB 1024
#define NPAD 8192

typedef unsigned long long u64;

__device__ float        g_part[MAXB];
__device__ unsigned int g_ctr;
__device__ unsigned int g_work;
// SoA staging, NEGATED (so diffs are f2add), padded
__device__ __align__(16) float g_nzx[NPAD];
__device__ __align__(16) float g_nzy[NPAD];
__device__ __align__(16) float g_nvx[NPAD];
__device__ __align__(16) float g_nvy[NPAD];

__device__ __forceinline__ float ex2_approx(float x) {
    float r; asm("ex2.approx.f32 %0, %1;" : "=f"(r) : "f"(x)); return r;
}
__device__ __forceinline__ float tanh_approx(float x) {
    float r; asm("tanh.approx.f32 %0, %1;" : "=f"(r) : "f"(x)); return r;
}
#define L2E 1.4426950408889634f
#define EK1 1.1283792f
#define EK3 0.100906f
#define SQRTPI_2 0.88622692545275801f

// ---------- packed f32x2 helpers ----------
__device__ __forceinline__ u64 f2pk(float lo, float hi) {
    u64 r; asm("mov.b64 %0, {%1, %2};" : "=l"(r) : "f"(lo), "f"(hi)); return r;
}
__device__ __forceinline__ void f2up(u64 v, float& lo, float& hi) {
    asm("mov.b64 {%0, %1}, %2;" : "=f"(lo), "=f"(hi) : "l"(v));
}
__device__ __forceinline__ u64 f2add(u64 a, u64 b) {
    u64 d; asm("add.rn.f32x2 %0, %1, %2;" : "=l"(d) : "l"(a), "l"(b)); return d;
}
__device__ __forceinline__ u64 f2mul(u64 a, u64 b) {
    u64 d; asm("mul.rn.f32x2 %0, %1, %2;" : "=l"(d) : "l"(a), "l"(b)); return d;
}
__device__ __forceinline__ u64 f2fma(u64 a, u64 b, u64 c) {
    u64 d; asm("fma.rn.f32x2 %0, %1, %2, %3;" : "=l"(d) : "l"(a), "l"(b), "l"(c)); return d;
}
__device__ __forceinline__ u64 f2rsqrt(u64 v) {
    float lo, hi; f2up(v, lo, hi); return f2pk(rsqrtf(lo), rsqrtf(hi));
}
__device__ __forceinline__ u64 f2tanh(u64 v) {
    float lo, hi; f2up(v, lo, hi); return f2pk(tanh_approx(lo), tanh_approx(hi));
}
__device__ __forceinline__ u64 ldg64(const float* p) {
    return __ldg(reinterpret_cast<const u64*>(p));
}

// ---------- scalar erf pieces ----------
__device__ __forceinline__ float erf_tanh(float x) {
    return tanh_approx(x * fmaf(EK3, x * x, EK1));
}
__device__ __forceinline__ float erf_small(float x, float u) {
    float p = fmaf(u, fmaf(u, fmaf(u, -2.3809524e-2f, 0.1f), -0.33333334f), 1.0f);
    return 1.1283791671f * x * p;
}

__device__ __forceinline__ float block_reduce_sum(float v) {
    __shared__ float s[32];
    int lane = threadIdx.x & 31;
    int w    = threadIdx.x >> 5;
    #pragma unroll
    for (int o = 16; o; o >>= 1) v += __shfl_xor_sync(0xffffffffu, v, o);
    if (lane == 0) s[w] = v;
    __syncthreads();
    v = (threadIdx.x < (TPB >> 5)) ? s[threadIdx.x] : 0.0f;
    if (w == 0) {
        #pragma unroll
        for (int o = 16; o; o >>= 1) v += __shfl_xor_sync(0xffffffffu, v, o);
    }
    return v;  // valid in thread 0
}

// scalar pair term (peel / general-t0 fallback; rare)
template <bool T0ZERO>
__device__ __forceinline__ float pair_term(float2 zi, float2 vi,
                                           float2 zj, float2 vj,
                                           float b, float t0, float tn) {
    float dzx = zi.x - zj.x, dzy = zi.y - zj.y;
    float dvx = vi.x - vj.x, dvy = vi.y - vj.y;
    float a2 = fmaf(dzx, dzx, dzy * dzy);
    float b2 = fmaf(dvx, dvx, dvy * dvy);
    float ab = fmaf(dzx, dvx, dzy * dvy);
    float rb = rsqrtf(b2);
    float bn = b2 * rb;
    float q  = ab * rb;
    float u  = q * q;
    float earg  = (b - a2) + u;
    float pref  = ex2_approx(earg * L2E) * (SQRTPI_2 * rb);
    float e1 = erf_tanh(fmaf(bn, tn, q));
    float e0 = T0ZERO ? erf_small(q, u) : erf_tanh(fmaf(bn, t0, q));
    return pref * (e1 - e0);
}

// ---------- prep: SoA-negate staging + counter reset ----------
__global__ void prep(const float2* __restrict__ z0,
                     const float2* __restrict__ v0, int n) {
    int i = blockIdx.x * blockDim.x + threadIdx.x;
    if (i == 0) { g_work = 0; g_ctr = 0; }
    if (i < NPAD) {
        float zx = 0.0f, zy = 0.0f, vx = 1e15f, vy = 0.0f;  // benign pad
        if (i < n) {
            float2 z = z0[i]; float2 v = v0[i];
            zx = z.x; zy = z.y; vx = v.x; vy = v.y;
        }
        g_nzx[i] = -zx; g_nzy[i] = -zy; g_nvx[i] = -vx; g_nvy[i] = -vy;
    }
}

// ---------- packed row: row i vs two j's per thread per iter ----------
__device__ __forceinline__ float row_pairs_packed(const float2* __restrict__ z0,
                                                  const float2* __restrict__ v0,
                                                  int i, int n,
                                                  float b, float tn, float eb886) {
    const float2 zi = __ldg(&z0[i]);
    const float2 vi = __ldg(&v0[i]);
    float acc_s = 0.0f;

    // peel pair (i, i+1) when i even (so packed base is even-aligned)
    if (((i & 1) == 0) && (i + 1 < n) && threadIdx.x == 0)
        acc_s = pair_term<true>(zi, vi, __ldg(&z0[i + 1]), __ldg(&v0[i + 1]),
                                b, 0.0f, tn);
    const int jb = (i + 2) & ~1;

    const u64 zix = f2pk(zi.x, zi.x), ziy = f2pk(zi.y, zi.y);
    const u64 vix = f2pk(vi.x, vi.x), viy = f2pk(vi.y, vi.y);

    const u64 NEG1 = f2pk(-1.0f, -1.0f);
    const u64 ONE2 = f2pk(1.0f, 1.0f);
    const u64 TN2  = f2pk(tn, tn);
    const u64 K1   = f2pk(EK1, EK1);
    const u64 K3   = f2pk(EK3, EK3);
    // e0 Taylor coeffs pre-scaled by 2/sqrt(pi), NEGATED (gives -e0 directly)
    const u64 T0n  = f2pk(-1.1283791671f, -1.1283791671f);
    const u64 T1n  = f2pk(0.3761263890f, 0.3761263890f);
    const u64 T2n  = f2pk(-0.1128379167f, -0.1128379167f);
    const u64 T3n  = f2pk(0.0268661706f, 0.0268661706f);
    // exp(w) Taylor coeffs
    const u64 C120 = f2pk(8.3333333e-3f, 8.3333333e-3f);
    const u64 C24  = f2pk(4.1666667e-2f, 4.1666667e-2f);
    const u64 C6_  = f2pk(0.16666667f, 0.16666667f);
    const u64 C2_  = f2pk(0.5f, 0.5f);
    const u64 EB   = f2pk(eb886, eb886);   // sqrt(pi)/2 * exp(b)

    u64 acc2 = 0;

    #pragma unroll 2
    for (int J = jb + 2 * (int)threadIdx.x; J < n; J += 2 * TPB) {
        u64 nzjx = ldg64(g_nzx + J);     // packed (-z[J].x, -z[J+1].x)
        u64 nzjy = ldg64(g_nzy + J);
        u64 nvjx = ldg64(g_nvx + J);
        u64 nvjy = ldg64(g_nvy + J);

        u64 dzx = f2add(zix, nzjx);      // zi - zj
        u64 dzy = f2add(ziy, nzjy);
        u64 dvx = f2add(vix, nvjx);
        u64 dvy = f2add(viy, nvjy);

        u64 a2 = f2fma(dzx, dzx, f2mul(dzy, dzy));
        u64 b2 = f2fma(dvx, dvx, f2mul(dvy, dvy));
        u64 ab = f2fma(dzx, dvx, f2mul(dzy, dvy));

        u64 rb = f2rsqrt(b2);            // MUFU x2
        u64 bn = f2mul(b2, rb);
        u64 q  = f2mul(ab, rb);
        u64 u  = f2mul(q, q);
        u64 w  = f2fma(a2, NEG1, u);     // q^2 - a2 in [-0.5, 0]

        // exp(w): degree-5 Taylor (FMA pipe)
        u64 p  = f2fma(w, C120, C24);
        p      = f2fma(w, p, C6_);
        p      = f2fma(w, p, C2_);
        p      = f2fma(w, p, ONE2);
        u64 P  = f2fma(w, p, ONE2);

        u64 pref = f2mul(f2mul(rb, EB), P);

        // -e0 = -erf(q), Taylor with negated coeffs (0 MUFU)
        u64 e0n = f2mul(q, f2fma(u, f2fma(u, f2fma(u, T3n, T2n), T1n), T0n));

        // e1 = erf(x1) via tanh identity
        u64 x1 = f2fma(bn, TN2, q);
        u64 h  = f2mul(x1, f2fma(K3, f2mul(x1, x1), K1));
        u64 e1 = f2tanh(h);              // MUFU x2

        acc2 = f2fma(pref, f2add(e1, e0n), acc2);
    }

    float lo, hi; f2up(acc2, lo, hi);
    return acc_s + lo + hi;
}

// scalar general-t0 row (rare path)
__device__ __forceinline__ float row_pairs_gen(const float2* __restrict__ z0,
                                               const float2* __restrict__ v0,
                                               int i, int n,
                                               float b, float t0, float tn) {
    const float2 zi = __ldg(&z0[i]);
    const float2 vi = __ldg(&v0[i]);
    float acc = 0.0f;
    for (int j = i + 1 + (int)threadIdx.x; j < n; j += TPB)
        acc += pair_term<false>(zi, vi, __ldg(&z0[j]), __ldg(&v0[j]), b, t0, tn);
    return acc;
}

__global__ void __launch_bounds__(TPB, 4)
cvm_fused(const int2*   __restrict__ idx,
          const float*  __restrict__ t,
          const float2* __restrict__ z0,
          const float2* __restrict__ v0,
          const float*  __restrict__ t0p,
          const float*  __restrict__ tnp,
          const float*  __restrict__ betap,
          float*        __restrict__ out,
          int n, int n_events) {
    const float b  = __ldg(betap);
    const float t0 = __ldg(t0p);
    const float tn = __ldg(tnp);
    const float eb886 = SQRTPI_2 * ex2_approx(b * L2E);
    float acc = 0.0f;

    // ---- pair term: atomic work-stealing over rows (descending cost) ----
    {
        const bool t0z = (t0 == 0.0f);
        __shared__ int s_row;
        for (;;) {
            if (threadIdx.x == 0)
                s_row = (int)atomicAdd(&g_work, 1u);
            __syncthreads();
            int r = s_row;
            __syncthreads();
            if (r >= n - 1) break;
            if (t0z) acc += row_pairs_packed(z0, v0, r, n, b, tn, eb886);
            else     acc += row_pairs_gen   (z0, v0, r, n, b, t0, tn);
        }
    }

    // ---- event term (all blocks, uniform grid-stride) ----
    {
        int stride = (int)gridDim.x * TPB;
        for (int e = (int)blockIdx.x * TPB + (int)threadIdx.x; e < n_events;
             e += stride) {
            int2  ij = __ldg(&idx[e]);
            float te = __ldg(&t[e]);
            float2 zi = __ldg(&z0[ij.x]);
            float2 zj = __ldg(&z0[ij.y]);
            float2 vi = __ldg(&v0[ij.x]);
            float2 vj = __ldg(&v0[ij.y]);
            float dx = fmaf(vi.x - vj.x, te, zi.x - zj.x);
            float dy = fmaf(vi.y - vj.y, te, zi.y - zj.y);
            acc = fmaf(dx, dx, acc);
            acc = fmaf(dy, dy, acc);
        }
    }

    float bs = block_reduce_sum(acc);
    __shared__ unsigned int s_rank;
    if (threadIdx.x == 0) {
        g_part[blockIdx.x] = bs;
        __threadfence();
        s_rank = atomicAdd(&g_ctr, 1u);
    }
    __syncthreads();

    if (s_rank == gridDim.x - 1) {
        __threadfence();
        double d = 0.0;
        for (int i = threadIdx.x; i < (int)gridDim.x; i += TPB)
            d += (double)g_part[i];
        __shared__ double sd[32];
        int lane = threadIdx.x & 31, w = threadIdx.x >> 5;
        #pragma unroll
        for (int o = 16; o; o >>= 1) d += __shfl_xor_sync(0xffffffffu, d, o);
        if (lane == 0) sd[w] = d;
        __syncthreads();
        d = (threadIdx.x < (TPB >> 5)) ? sd[threadIdx.x] : 0.0;
        if (w == 0) {
            #pragma unroll
            for (int o = 16; o; o >>= 1) d += __shfl_xor_sync(0xffffffffu, d, o);
        }
        if (threadIdx.x == 0)
            out[0] = (float)((double)n_events * (double)b - d);
    }
}

extern "C" void kernel_launch(void* const* d_in, const int* in_sizes, int n_in,
                              void* d_out, int out_size) {
    const int2*   idx  = (const int2*)d_in[0];    // (N_EVENTS, 2) int32
    const float*  t    = (const float*)d_in[1];   // (N_EVENTS,)
    const float*  t0   = (const float*)d_in[2];   // scalar
    const float*  tn   = (const float*)d_in[3];   // scalar
    const float2* z0   = (const float2*)d_in[4];  // (N_POINTS, 2)
    const float2* v0   = (const float2*)d_in[5];  // (N_POINTS, 2)
    const float*  beta = (const float*)d_in[6];   // (1,1)

    const int n_events = in_sizes[1];
    const int n_points = in_sizes[4] / 2;

    prep<<<(NPAD + 255) / 256, 256>>>(z0, v0, n_points);

    // 4 blocks/SM x 148 SMs, one wave; rows distributed by atomic stealing.
    int grid = 4 * 148;
    cvm_fused<<<grid, TPB>>>(idx, t, z0, v0, t0, tn, beta,
                             (float*)d_out, n_points, n_events);
}

// round 10
// speedup vs baseline: 1.0645x; 1.0645x over previous
#include <cuda_runtime.h>

#define TPB  256
#define MAXB 1024
#define NPAD 8192

typedef unsigned long long u64;

__device__ float        g_part[MAXB];
__device__ unsigned int g_ctr;
// SoA staging, NEGATED (so diffs are f2add), padded
__device__ __align__(16) float g_nzx[NPAD];
__device__ __align__(16) float g_nzy[NPAD];
__device__ __align__(16) float g_nvx[NPAD];
__device__ __align__(16) float g_nvy[NPAD];

__device__ __forceinline__ float ex2_approx(float x) {
    float r; asm("ex2.approx.f32 %0, %1;" : "=f"(r) : "f"(x)); return r;
}
__device__ __forceinline__ float tanh_approx(float x) {
    float r; asm("tanh.approx.f32 %0, %1;" : "=f"(r) : "f"(x)); return r;
}
#define L2E 1.4426950408889634f
#define EK1 1.1283792f
#define EK3 0.100906f
#define SQRTPI_2 0.88622692545275801f

// ---------- packed f32x2 helpers ----------
__device__ __forceinline__ u64 f2pk(float lo, float hi) {
    u64 r; asm("mov.b64 %0, {%1, %2};" : "=l"(r) : "f"(lo), "f"(hi)); return r;
}
__device__ __forceinline__ void f2up(u64 v, float& lo, float& hi) {
    asm("mov.b64 {%0, %1}, %2;" : "=f"(lo), "=f"(hi) : "l"(v));
}
__device__ __forceinline__ u64 f2add(u64 a, u64 b) {
    u64 d; asm("add.rn.f32x2 %0, %1, %2;" : "=l"(d) : "l"(a), "l"(b)); return d;
}
__device__ __forceinline__ u64 f2mul(u64 a, u64 b) {
    u64 d; asm("mul.rn.f32x2 %0, %1, %2;" : "=l"(d) : "l"(a), "l"(b)); return d;
}
__device__ __forceinline__ u64 f2fma(u64 a, u64 b, u64 c) {
    u64 d; asm("fma.rn.f32x2 %0, %1, %2, %3;" : "=l"(d) : "l"(a), "l"(b), "l"(c)); return d;
}
__device__ __forceinline__ u64 f2rsqrt(u64 v) {
    float lo, hi; f2up(v, lo, hi); return f2pk(rsqrtf(lo), rsqrtf(hi));
}
__device__ __forceinline__ u64 f2tanh(u64 v) {
    float lo, hi; f2up(v, lo, hi); return f2pk(tanh_approx(lo), tanh_approx(hi));
}
__device__ __forceinline__ u64 ldg64(const float* p) {
    return __ldg(reinterpret_cast<const u64*>(p));
}

// ---------- scalar erf pieces ----------
__device__ __forceinline__ float erf_tanh(float x) {
    return tanh_approx(x * fmaf(EK3, x * x, EK1));
}
__device__ __forceinline__ float erf_small(float x, float u) {
    float p = fmaf(u, fmaf(u, fmaf(u, -2.3809524e-2f, 0.1f), -0.33333334f), 1.0f);
    return 1.1283791671f * x * p;
}

__device__ __forceinline__ float block_reduce_sum(float v) {
    __shared__ float s[32];
    int lane = threadIdx.x & 31;
    int w    = threadIdx.x >> 5;
    #pragma unroll
    for (int o = 16; o; o >>= 1) v += __shfl_xor_sync(0xffffffffu, v, o);
    if (lane == 0) s[w] = v;
    __syncthreads();
    v = (threadIdx.x < (TPB >> 5)) ? s[threadIdx.x] : 0.0f;
    if (w == 0) {
        #pragma unroll
        for (int o = 16; o; o >>= 1) v += __shfl_xor_sync(0xffffffffu, v, o);
    }
    return v;  // valid in thread 0
}

// scalar pair term (peel / general-t0 fallback; rare)
template <bool T0ZERO>
__device__ __forceinline__ float pair_term(float2 zi, float2 vi,
                                           float2 zj, float2 vj,
                                           float b, float t0, float tn) {
    float dzx = zi.x - zj.x, dzy = zi.y - zj.y;
    float dvx = vi.x - vj.x, dvy = vi.y - vj.y;
    float a2 = fmaf(dzx, dzx, dzy * dzy);
    float b2 = fmaf(dvx, dvx, dvy * dvy);
    float ab = fmaf(dzx, dvx, dzy * dvy);
    float rb = rsqrtf(b2);
    float bn = b2 * rb;
    float q  = ab * rb;
    float u  = q * q;
    float earg  = (b - a2) + u;
    float pref  = ex2_approx(earg * L2E) * (SQRTPI_2 * rb);
    float e1 = erf_tanh(fmaf(bn, tn, q));
    float e0 = T0ZERO ? erf_small(q, u) : erf_tanh(fmaf(bn, t0, q));
    return pref * (e1 - e0);
}

// ---------- prep: SoA-negate staging + counter reset ----------
__global__ void prep(const float2* __restrict__ z0,
                     const float2* __restrict__ v0, int n) {
    int i = blockIdx.x * blockDim.x + threadIdx.x;
    if (i == 0) g_ctr = 0;
    if (i < NPAD) {
        float zx = 0.0f, zy = 0.0f, vx = 1e15f, vy = 0.0f;  // benign pad
        if (i < n) {
            float2 z = z0[i]; float2 v = v0[i];
            zx = z.x; zy = z.y; vx = v.x; vy = v.y;
        }
        g_nzx[i] = -zx; g_nzy[i] = -zy; g_nvx[i] = -vx; g_nvy[i] = -vy;
    }
}

// ---------- dual-row group, SoA packed-j body (t0 == 0 fast path) ----------
// 4 pairs per iteration: 2 broadcast i-rows x 2 packed j's per thread.
__device__ __forceinline__ float group_pairs_soa(const float2* __restrict__ z0,
                                                 const float2* __restrict__ v0,
                                                 int g, int n,
                                                 float b, float tn, float eb886) {
    const int i0 = 2 * g;
    if (i0 >= n - 1) return 0.0f;
    const int i1 = i0 + 1;

    const float2 zi0 = __ldg(&z0[i0]);
    const float2 vi0 = __ldg(&v0[i0]);
    float acc_s = 0.0f;

    if (i1 >= n) {  // odd-n tail: single row, scalar
        for (int j = i0 + 1 + (int)threadIdx.x; j < n; j += TPB)
            acc_s += pair_term<true>(zi0, vi0, __ldg(&z0[j]), __ldg(&v0[j]),
                                     b, 0.0f, tn);
        return acc_s;
    }

    const float2 zi1 = __ldg(&z0[i1]);
    const float2 vi1 = __ldg(&v0[i1]);
    if (threadIdx.x == 0)  // peel pair (i0, i1)
        acc_s = pair_term<true>(zi0, vi0, zi1, vi1, b, 0.0f, tn);

    // broadcast i-row values as packed duplicates
    const u64 zx0 = f2pk(zi0.x, zi0.x), zy0 = f2pk(zi0.y, zi0.y);
    const u64 vx0 = f2pk(vi0.x, vi0.x), vy0 = f2pk(vi0.y, vi0.y);
    const u64 zx1 = f2pk(zi1.x, zi1.x), zy1 = f2pk(zi1.y, zi1.y);
    const u64 vx1 = f2pk(vi1.x, vi1.x), vy1 = f2pk(vi1.y, vi1.y);

    const u64 NEG1 = f2pk(-1.0f, -1.0f);
    const u64 ONE2 = f2pk(1.0f, 1.0f);
    const u64 TN2  = f2pk(tn, tn);
    const u64 K1   = f2pk(EK1, EK1);
    const u64 K3   = f2pk(EK3, EK3);
    // e0 Taylor coeffs pre-scaled by 2/sqrt(pi), NEGATED (gives -e0)
    const u64 T0n  = f2pk(-1.1283791671f, -1.1283791671f);
    const u64 T1n  = f2pk(0.3761263890f, 0.3761263890f);
    const u64 T2n  = f2pk(-0.1128379167f, -0.1128379167f);
    const u64 T3n  = f2pk(0.0268661706f, 0.0268661706f);
    // exp(w) Taylor coeffs
    const u64 C120 = f2pk(8.3333333e-3f, 8.3333333e-3f);
    const u64 C24  = f2pk(4.1666667e-2f, 4.1666667e-2f);
    const u64 C6_  = f2pk(0.16666667f, 0.16666667f);
    const u64 C2_  = f2pk(0.5f, 0.5f);
    const u64 EB   = f2pk(eb886, eb886);   // sqrt(pi)/2 * exp(b)

    u64 accA = 0, accB = 0;   // two independent chains

    const int jb = i0 + 2;    // even (i0 = 2g), so packed loads are aligned
    for (int J = jb + 2 * (int)threadIdx.x; J < n; J += 2 * TPB) {
        u64 nzjx = ldg64(g_nzx + J);     // (-z[J].x, -z[J+1].x)
        u64 nzjy = ldg64(g_nzy + J);
        u64 nvjx = ldg64(g_nvx + J);
        u64 nvjy = ldg64(g_nvy + J);

        // ---- row i0 ----
        {
            u64 dzx = f2add(zx0, nzjx);
            u64 dzy = f2add(zy0, nzjy);
            u64 dvx = f2add(vx0, nvjx);
            u64 dvy = f2add(vy0, nvjy);
            u64 a2 = f2fma(dzx, dzx, f2mul(dzy, dzy));
            u64 b2 = f2fma(dvx, dvx, f2mul(dvy, dvy));
            u64 ab = f2fma(dzx, dvx, f2mul(dzy, dvy));
            u64 rb = f2rsqrt(b2);
            u64 bn = f2mul(b2, rb);
            u64 q  = f2mul(ab, rb);
            u64 u  = f2mul(q, q);
            u64 w  = f2fma(a2, NEG1, u);
            u64 p  = f2fma(w, C120, C24);
            p      = f2fma(w, p, C6_);
            p      = f2fma(w, p, C2_);
            p      = f2fma(w, p, ONE2);
            u64 P  = f2fma(w, p, ONE2);
            u64 pref = f2mul(f2mul(rb, EB), P);
            u64 e0n = f2mul(q, f2fma(u, f2fma(u, f2fma(u, T3n, T2n), T1n), T0n));
            u64 x1 = f2fma(bn, TN2, q);
            u64 h  = f2mul(x1, f2fma(K3, f2mul(x1, x1), K1));
            u64 e1 = f2tanh(h);
            accA = f2fma(pref, f2add(e1, e0n), accA);
        }
        // ---- row i1 ----
        {
            u64 dzx = f2add(zx1, nzjx);
            u64 dzy = f2add(zy1, nzjy);
            u64 dvx = f2add(vx1, nvjx);
            u64 dvy = f2add(vy1, nvjy);
            u64 a2 = f2fma(dzx, dzx, f2mul(dzy, dzy));
            u64 b2 = f2fma(dvx, dvx, f2mul(dvy, dvy));
            u64 ab = f2fma(dzx, dvx, f2mul(dzy, dvy));
            u64 rb = f2rsqrt(b2);
            u64 bn = f2mul(b2, rb);
            u64 q  = f2mul(ab, rb);
            u64 u  = f2mul(q, q);
            u64 w  = f2fma(a2, NEG1, u);
            u64 p  = f2fma(w, C120, C24);
            p      = f2fma(w, p, C6_);
            p      = f2fma(w, p, C2_);
            p      = f2fma(w, p, ONE2);
            u64 P  = f2fma(w, p, ONE2);
            u64 pref = f2mul(f2mul(rb, EB), P);
            u64 e0n = f2mul(q, f2fma(u, f2fma(u, f2fma(u, T3n, T2n), T1n), T0n));
            u64 x1 = f2fma(bn, TN2, q);
            u64 h  = f2mul(x1, f2fma(K3, f2mul(x1, x1), K1));
            u64 e1 = f2tanh(h);
            accB = f2fma(pref, f2add(e1, e0n), accB);
        }
    }

    float lo, hi; f2up(f2add(accA, accB), lo, hi);
    return acc_s + lo + hi;
}

// scalar general-t0 group (rare path)
__device__ __forceinline__ float group_pairs_gen(const float2* __restrict__ z0,
                                                 const float2* __restrict__ v0,
                                                 int g, int n,
                                                 float b, float t0, float tn) {
    int i0 = 2 * g;
    if (i0 >= n - 1) return 0.0f;
    int i1 = i0 + 1;
    const float2 zi0 = __ldg(&z0[i0]);
    const float2 vi0 = __ldg(&v0[i0]);
    float acc = 0.0f;
    for (int j = i0 + 1 + (int)threadIdx.x; j < n; j += TPB)
        acc += pair_term<false>(zi0, vi0, __ldg(&z0[j]), __ldg(&v0[j]), b, t0, tn);
    if (i1 < n) {
        const float2 zi1 = __ldg(&z0[i1]);
        const float2 vi1 = __ldg(&v0[i1]);
        for (int j = i1 + 1 + (int)threadIdx.x; j < n; j += TPB)
            acc += pair_term<false>(zi1, vi1, __ldg(&z0[j]), __ldg(&v0[j]), b, t0, tn);
    }
    return acc;
}

__global__ void __launch_bounds__(TPB, 4)
cvm_fused(const int2*   __restrict__ idx,
          const float*  __restrict__ t,
          const float2* __restrict__ z0,
          const float2* __restrict__ v0,
          const float*  __restrict__ t0p,
          const float*  __restrict__ tnp,
          const float*  __restrict__ betap,
          float*        __restrict__ out,
          int n, int n_events, int ngroups) {
    const float b  = __ldg(betap);
    const float t0 = __ldg(t0p);
    const float tn = __ldg(tnp);
    const float eb886 = SQRTPI_2 * ex2_approx(b * L2E);
    float acc = 0.0f;

    // ---- pair term: static snake over dual-row groups (no atomics) ----
    {
        const int P = gridDim.x;
        const bool t0z = (t0 == 0.0f);
        for (int p = 0; ; p++) {
            int base = p * P;
            if (base >= ngroups) break;
            int bb = (p & 1) ? (P - 1 - (int)blockIdx.x) : (int)blockIdx.x;
            int g  = base + bb;
            if (g < ngroups) {
                if (t0z) acc += group_pairs_soa(z0, v0, g, n, b, tn, eb886);
                else     acc += group_pairs_gen(z0, v0, g, n, b, t0, tn);
            }
        }
    }

    // ---- event term (all blocks, uniform grid-stride) ----
    {
        int stride = (int)gridDim.x * TPB;
        for (int e = (int)blockIdx.x * TPB + (int)threadIdx.x; e < n_events;
             e += stride) {
            int2  ij = __ldg(&idx[e]);
            float te = __ldg(&t[e]);
            float2 zi = __ldg(&z0[ij.x]);
            float2 zj = __ldg(&z0[ij.y]);
            float2 vi = __ldg(&v0[ij.x]);
            float2 vj = __ldg(&v0[ij.y]);
            float dx = fmaf(vi.x - vj.x, te, zi.x - zj.x);
            float dy = fmaf(vi.y - vj.y, te, zi.y - zj.y);
            acc = fmaf(dx, dx, acc);
            acc = fmaf(dy, dy, acc);
        }
    }

    float bs = block_reduce_sum(acc);
    __shared__ unsigned int s_rank;
    if (threadIdx.x == 0) {
        g_part[blockIdx.x] = bs;
        __threadfence();
        s_rank = atomicAdd(&g_ctr, 1u);
    }
    __syncthreads();

    if (s_rank == gridDim.x - 1) {
        __threadfence();
        double d = 0.0;
        for (int i = threadIdx.x; i < (int)gridDim.x; i += TPB)
            d += (double)g_part[i];
        __shared__ double sd[32];
        int lane = threadIdx.x & 31, w = threadIdx.x >> 5;
        #pragma unroll
        for (int o = 16; o; o >>= 1) d += __shfl_xor_sync(0xffffffffu, d, o);
        if (lane == 0) sd[w] = d;
        __syncthreads();
        d = (threadIdx.x < (TPB >> 5)) ? sd[threadIdx.x] : 0.0;
        if (w == 0) {
            #pragma unroll
            for (int o = 16; o; o >>= 1) d += __shfl_xor_sync(0xffffffffu, d, o);
        }
        if (threadIdx.x == 0)
            out[0] = (float)((double)n_events * (double)b - d);
    }
}

extern "C" void kernel_launch(void* const* d_in, const int* in_sizes, int n_in,
                              void* d_out, int out_size) {
    const int2*   idx  = (const int2*)d_in[0];    // (N_EVENTS, 2) int32
    const float*  t    = (const float*)d_in[1];   // (N_EVENTS,)
    const float*  t0   = (const float*)d_in[2];   // scalar
    const float*  tn   = (const float*)d_in[3];   // scalar
    const float2* z0   = (const float2*)d_in[4];  // (N_POINTS, 2)
    const float2* v0   = (const float2*)d_in[5];  // (N_POINTS, 2)
    const float*  beta = (const float*)d_in[6];   // (1,1)

    const int n_events = in_sizes[1];
    const int n_points = in_sizes[4] / 2;

    const int ngroups = (n_points + 1) / 2;   // dual-row groups

    prep<<<(NPAD + 255) / 256, 256>>>(z0, v0, n_points);

    // 4 blocks/SM x 148 SMs: one wave, static snake balance.
    int grid = 4 * 148;
    cvm_fused<<<grid, TPB>>>(idx, t, z0, v0, t0, tn, beta,
                             (float*)d_out, n_points, n_events, ngroups);
}